// round 16
// baseline (speedup 1.0000x reference)
#include <cuda_runtime.h>
#include <math.h>
#include <stdint.h>

#define BB 16
#define TT 256
#define DD 128
#define HH 128
#define LL 4
#define GG (4*HH)      // 512 gates
#define NC 10
#define EPSF 1e-5f
#define BT (BB*TT)     // 4096
#define CC 32          // chunk length (per-diagonal wave)
#define KK (TT/CC)     // 8 chunks
#define NDIAG (LL+KK-1)

// ---------------- scratch (device globals; no allocation allowed) ----------------
__device__ float g_x2[BT*DD];
__device__ float g_hall[LL*BT*HH];    // per-layer hidden outputs
__device__ float g_hstate[LL*BB*HH];  // chunk-boundary h
__device__ float g_cstate[LL*BB*HH];  // chunk-boundary c
__device__ float g_ph[BT*HH];
__device__ float g_pxr[BT*HH];
__device__ float g_mu[DD];
__device__ float g_sd[DD];
__device__ float g_hmu[BB*HH];
__device__ float g_hrs[BB*HH];
__device__ float g_fc_scratch[BB*NC];
__device__ float g_map_scratch[BT*DD];

// ---------------- helpers ----------------
__device__ __forceinline__ float warpSum(float v) {
    #pragma unroll
    for (int o = 16; o > 0; o >>= 1) v += __shfl_xor_sync(0xffffffffu, v, o);
    return v;
}
// HW tanh (sm_75+): 1 MUFU op, ~2e-5 rel err
__device__ __forceinline__ float ftanh(float x) {
    float y;
    asm("tanh.approx.f32 %0, %1;" : "=f"(y) : "f"(x));
    return y;
}
__device__ __forceinline__ float fsig2(float x) {            // sigmoid via HW tanh
    return fmaf(ftanh(x * 0.5f), 0.5f, 0.5f);
}
__device__ __forceinline__ unsigned int smem_u32(const void* p) {
    unsigned int a;
    asm("{ .reg .u64 t; cvta.to.shared.u64 t, %1; cvt.u32.u64 %0, t; }" : "=r"(a) : "l"(p));
    return a;
}
__device__ __forceinline__ unsigned int mapa_u32(unsigned int local, unsigned int rank) {
    unsigned int r;
    asm("mapa.shared::cluster.u32 %0, %1, %2;" : "=r"(r) : "r"(local), "r"(rank));
    return r;
}
__device__ __forceinline__ void fma2(unsigned long long& acc, unsigned long long a, unsigned long long b) {
    asm("fma.rn.f32x2 %0, %1, %2, %0;" : "+l"(acc) : "l"(a), "l"(b));
}
__device__ __forceinline__ void mbar_init(unsigned int addr, unsigned int cnt) {
    asm volatile("mbarrier.init.shared.b64 [%0], %1;" :: "r"(addr), "r"(cnt) : "memory");
}
__device__ __forceinline__ void mbar_expect_tx(unsigned int addr, unsigned int bytes) {
    asm volatile("mbarrier.arrive.expect_tx.shared.b64 _, [%0], %1;" :: "r"(addr), "r"(bytes) : "memory");
}
__device__ __forceinline__ void st_async_f32(unsigned int addr, float v, unsigned int mbar) {
    asm volatile("st.async.shared::cluster.mbarrier::complete_tx::bytes.b32 [%0], %1, [%2];"
                 :: "r"(addr), "r"(__float_as_uint(v)), "r"(mbar) : "memory");
}
__device__ __forceinline__ void bar_wait_acq_cta(unsigned int addr, int parity) {
    asm volatile(
        "{\n\t"
        ".reg .pred P;\n\t"
        "BWL_%=:\n\t"
        "mbarrier.try_wait.parity.acquire.cta.shared::cta.b64 P, [%0], %1, 0x989680;\n\t"
        "@P bra BWD_%=;\n\t"
        "bra BWL_%=;\n\t"
        "BWD_%=:\n\t"
        "}"
        :: "r"(addr), "r"(parity) : "memory");
}

// ---------------- per-feature global mean / std (ddof=1), std+EPS ----------------
__global__ void stats_kernel(const float* __restrict__ x) {
    int d = blockIdx.x;
    float s = 0.f, s2 = 0.f;
    for (int i = threadIdx.x; i < BT; i += blockDim.x) {
        float v = x[i*DD + d];
        s += v; s2 += v*v;
    }
    __shared__ float sh[64];
    s = warpSum(s); s2 = warpSum(s2);
    int w = threadIdx.x >> 5, ln = threadIdx.x & 31;
    if (ln == 0) { sh[w] = s; sh[32+w] = s2; }
    __syncthreads();
    if (threadIdx.x == 0) {
        float S = 0.f, S2 = 0.f;
        int nw = blockDim.x >> 5;
        for (int i = 0; i < nw; i++) { S += sh[i]; S2 += sh[32+i]; }
        float m = S / (float)BT;
        float var = (S2 - (float)BT*m*m) / ((float)BT - 1.0f);
        g_mu[d] = m;
        g_sd[d] = sqrtf(var) + EPSF;
    }
}

// ---------------- global normalize + instance norm over T, fused ----------------
__global__ void norm1_kernel(const float* __restrict__ x) {
    int b = blockIdx.x / DD, d = blockIdx.x % DD;
    int t = threadIdx.x;
    float mu = g_mu[d], sd = g_sd[d];
    float v = x[((b*TT) + t)*DD + d];
    float x1 = (v - mu) / sd;
    __shared__ float sh[16];
    float s = warpSum(x1), s2 = warpSum(x1*x1);
    int w = t >> 5, ln = t & 31;
    if (ln == 0) { sh[w] = s; sh[8+w] = s2; }
    __syncthreads();
    __shared__ float mm, rs;
    if (t == 0) {
        float S = 0.f, S2 = 0.f;
        for (int i = 0; i < 8; i++) { S += sh[i]; S2 += sh[8+i]; }
        float m = S / (float)TT;
        float var = S2 / (float)TT - m*m;
        mm = m; rs = rsqrtf(var + EPSF);
    }
    __syncthreads();
    g_x2[((b*TT) + t)*DD + d] = (x1 - mm) * rs;
}

// ---------------- column stats over T per (b,c) ----------------
__global__ void __launch_bounds__(256) colstats_kernel(
    const float* __restrict__ in, float* __restrict__ mu_o, float* __restrict__ rs_o)
{
    int b = blockIdx.x;
    int w = threadIdx.x >> 5, ln = threadIdx.x & 31;
    __shared__ float ws[8][HH], ws2[8][HH];
    float s[4] = {0,0,0,0}, s2[4] = {0,0,0,0};
    const float* base = in + (size_t)b*TT*HH;
    for (int t = w*32; t < (w+1)*32; t++) {
        const float* row = base + (size_t)t*HH;
        #pragma unroll
        for (int j = 0; j < 4; j++) {
            float v = row[ln + 32*j];
            s[j] += v; s2[j] += v*v;
        }
    }
    #pragma unroll
    for (int j = 0; j < 4; j++) { ws[w][ln + 32*j] = s[j]; ws2[w][ln + 32*j] = s2[j]; }
    __syncthreads();
    if (threadIdx.x < HH) {
        int c = threadIdx.x;
        float S = 0.f, S2 = 0.f;
        #pragma unroll
        for (int i = 0; i < 8; i++) { S += ws[i][c]; S2 += ws2[i][c]; }
        float m = S / (float)TT;
        float var = S2 / (float)TT - m*m;
        mu_o[b*HH + c] = m;
        rs_o[b*HH + c] = rsqrtf(var + EPSF);
    }
}

// ---------------- dual projection GEMM: ph (normalized) and pxr in ONE launch ----
__global__ void __launch_bounds__(128, 4) proj_dual_kernel(
    const float* __restrict__ A1, const float* __restrict__ W1,
    const float* __restrict__ b1, const float* __restrict__ mu,
    const float* __restrict__ rs, float* __restrict__ C1,
    const float* __restrict__ A2, const float* __restrict__ W2,
    const float* __restrict__ b2, float* __restrict__ C2)
{
    __shared__ __align__(16) float As[16*128];
    const bool second = blockIdx.x >= 256;
    const int m0 = (second ? (blockIdx.x - 256) : blockIdx.x) * 16;
    const float* A = second ? A2 : A1;
    const float* W = second ? W2 : W1;
    const float* bb = second ? b2 : b1;
    float* C = second ? C2 : C1;

    if (!second) {
        __shared__ float mu_s[128], rs_s[128];
        int b = m0 / TT;
        if (threadIdx.x < 128) {
            mu_s[threadIdx.x] = mu[b*HH + threadIdx.x];
            rs_s[threadIdx.x] = rs[b*HH + threadIdx.x];
        }
        __syncthreads();
        for (int idx = threadIdx.x; idx < 16*128; idx += blockDim.x) {
            int k = idx & 127;
            As[idx] = (A[m0*128 + idx] - mu_s[k]) * rs_s[k];
        }
    } else {
        for (int idx = threadIdx.x; idx < 16*128; idx += blockDim.x)
            As[idx] = A[m0*128 + idx];
    }
    __syncthreads();
    int j = threadIdx.x;
    float bias = bb[j];
    float acc[16];
    #pragma unroll
    for (int mi = 0; mi < 16; mi++) acc[mi] = bias;
    const float4* W4 = reinterpret_cast<const float4*>(W) + j*32;
    for (int k4 = 0; k4 < 32; k4++) {
        float4 w = W4[k4];
        #pragma unroll
        for (int mi = 0; mi < 16; mi++) {
            float4 a = *reinterpret_cast<const float4*>(&As[mi*128 + k4*4]);
            acc[mi] += a.x*w.x + a.y*w.y + a.z*w.z + a.w*w.w;
        }
    }
    #pragma unroll
    for (int mi = 0; mi < 16; mi++) C[(m0+mi)*HH + j] = acc[mi];
}

// ==================== chunked wavefront LSTM (launch-per-diagonal, R8 engine) ====
// One diagonal d: cells (l, k=d-l). Per cell: 16 batches x 2-CTA cluster.
// CTA q owns units [64q,64q+64) = 256 gate rows; 256 threads, full 128-weight
// Whh row per thread (regs). Phase A streams Wih for ALL layers (layer 0 reads
// x2 directly — no standalone input GEMM). HW tanh activations.
__global__ void __launch_bounds__(256, 1) __cluster_dims__(2, 1, 1)
lstm_wave(int lmin, int d,
          const float* __restrict__ x2,
          const float* __restrict__ Wih, const float* __restrict__ Whh,
          const float* __restrict__ bih, const float* __restrict__ bhh,
          float* __restrict__ hall, float* __restrict__ hstate, float* __restrict__ cstate)
{
    extern __shared__ float dyn[];
    float* gin_s = dyn;                // CC*256
    float* hin_s = dyn + CC*256;       // CC*128
    __shared__ __align__(16) float hbuf[2][HH];
    __shared__ float gates_s[256];
    __shared__ __align__(8) unsigned long long barF[2];

    const int cell = blockIdx.x >> 5;
    const int b    = (blockIdx.x >> 1) & 15;
    const int q    = blockIdx.x & 1;
    const int l    = lmin + cell;
    const int k    = d - l;
    const int tid  = threadIdx.x;
    const int gtype = tid >> 6, u = tid & 63;
    const int row_g = gtype*HH + q*64 + u;

    unsigned long long w[64];   // 128 weight floats; Wih (phase A) then Whh (phase B)

    // ---------- Phase A: gin_s[s][tid] = Wih . input(s) + bias ----------
    {
        const float* hsrc = (l == 0)
            ? (x2 + ((size_t)(b*TT + k*CC))*DD)
            : (hall + ((size_t)(l-1)*BT + b*TT + k*CC)*HH);
        for (int idx = tid; idx < CC*HH; idx += 256) hin_s[idx] = hsrc[idx];
        {
            const unsigned long long* Wp =
                reinterpret_cast<const unsigned long long*>(Wih + ((size_t)l*GG + row_g)*HH);
            #pragma unroll
            for (int i = 0; i < 64; i++) w[i] = Wp[i];
        }
        float bias = bih[l*GG + row_g] + bhh[l*GG + row_g];
        __syncthreads();
        #pragma unroll 1
        for (int s = 0; s < CC; s++) {
            const ulonglong2* H = reinterpret_cast<const ulonglong2*>(&hin_s[s*HH]);
            unsigned long long a0 = 0ULL, a1 = 0ULL;
            #pragma unroll
            for (int i = 0; i < 32; i++) {
                ulonglong2 h2 = H[i];
                fma2(a0, w[2*i],   h2.x);
                fma2(a1, w[2*i+1], h2.y);
            }
            gin_s[s*256 + tid] = bias
                + __uint_as_float((unsigned)(a0 & 0xffffffffULL))
                + __uint_as_float((unsigned)(a0 >> 32))
                + __uint_as_float((unsigned)(a1 & 0xffffffffULL))
                + __uint_as_float((unsigned)(a1 >> 32));
        }
    }

    // ---------- Phase B setup: Whh row, self k-half first ----------
    {
        const float* Wrow = Whh + ((size_t)l*GG + row_g)*HH;
        const unsigned long long* WpS =
            reinterpret_cast<const unsigned long long*>(Wrow + q*64);
        const unsigned long long* WpP =
            reinterpret_cast<const unsigned long long*>(Wrow + (q^1)*64);
        #pragma unroll
        for (int i = 0; i < 32; i++) { w[i] = WpS[i]; w[32+i] = WpP[i]; }
    }
    const int sidx = (l*BB + b)*HH;
    if (tid < HH) hbuf[0][tid] = (k == 0) ? 0.f : hstate[sidx + tid];
    float c = 0.f;
    if (tid < 64 && k > 0) c = cstate[sidx + q*64 + tid];

    const unsigned int barF_loc = smem_u32(&barF[0]);
    if (tid == 0) {
        mbar_init(barF_loc,     1);
        mbar_init(barF_loc + 8, 1);
    }
    __syncthreads();
    if (tid == 64) {
        mbar_expect_tx(barF_loc + 8, 256u);   // step 1 (slot 1)
        mbar_expect_tx(barF_loc,     256u);   // step 2 (slot 0)
    }
    unsigned int dstH[2], dstB[2];
    if (tid < 64) {
        unsigned int h0 = smem_u32(&hbuf[0][q*64 + tid]);
        unsigned int h1 = smem_u32(&hbuf[1][q*64 + tid]);
        unsigned int pr = q ^ 1;
        dstH[0] = mapa_u32(h0, pr);
        dstH[1] = mapa_u32(h1, pr);
        dstB[0] = mapa_u32(barF_loc,     pr);
        dstB[1] = mapa_u32(barF_loc + 8, pr);
    }
    __syncthreads();
    asm volatile("barrier.cluster.arrive.aligned;" ::: "memory");
    asm volatile("barrier.cluster.wait.aligned;"   ::: "memory");

    float* hout = hall + ((size_t)l*BT + b*TT + k*CC)*HH + q*64;
    int pF[2] = {0, 0};
    const int selfOff = q*64, partOff = (q^1)*64;

    // ---------- Phase B: CC recurrence steps ----------
    #pragma unroll 1
    for (int s = 0; s < CC; s++) {
        const int sl = s & 1;
        // self-half dot first (hides partner transit)
        unsigned long long a0 = 0ULL, a1 = 0ULL;
        {
            const ulonglong2* Hs = reinterpret_cast<const ulonglong2*>(&hbuf[sl][selfOff]);
            #pragma unroll
            for (int i = 0; i < 16; i++) {
                ulonglong2 h2 = Hs[i];
                fma2(a0, w[2*i],   h2.x);
                fma2(a1, w[2*i+1], h2.y);
            }
        }
        float gval = gin_s[s*256 + tid];
        if (s >= 1) {
            bar_wait_acq_cta(barF_loc + 8*sl, pF[sl]); pF[sl] ^= 1;
            if (tid == 64 && s + 2 < CC) mbar_expect_tx(barF_loc + 8*sl, 256u);
        }
        {
            const ulonglong2* Hp = reinterpret_cast<const ulonglong2*>(&hbuf[sl][partOff]);
            #pragma unroll
            for (int i = 0; i < 16; i++) {
                ulonglong2 h2 = Hp[i];
                fma2(a0, w[32 + 2*i], h2.x);
                fma2(a1, w[33 + 2*i], h2.y);
            }
        }
        gates_s[tid] = gval
            + __uint_as_float((unsigned)(a0 & 0xffffffffULL))
            + __uint_as_float((unsigned)(a0 >> 32))
            + __uint_as_float((unsigned)(a1 & 0xffffffffULL))
            + __uint_as_float((unsigned)(a1 >> 32));
        __syncthreads();

        if (tid < 64) {
            float gi = gates_s[tid],       gf = gates_s[64 + tid];
            float gg = gates_s[128 + tid], go = gates_s[192 + tid];
            float si = fsig2(gi), sf = fsig2(gf), so = fsig2(go);
            float tg = ftanh(gg);
            c = sf*c + si*tg;
            float hn = so * ftanh(c);
            if (s + 1 < CC) {
                int ns = (s + 1) & 1;
                st_async_f32(dstH[ns], hn, dstB[ns]);  // remote 64 via tx barrier
                hbuf[ns][selfOff + tid] = hn;          // own 64 via STS
            } else {
                hstate[sidx + selfOff + tid] = hn;
                cstate[sidx + selfOff + tid] = c;
            }
            hout[(size_t)s*HH + tid] = hn;
        }
        __syncthreads();
    }
    asm volatile("barrier.cluster.arrive.aligned;" ::: "memory");
    asm volatile("barrier.cluster.wait.aligned;"   ::: "memory");
}

// ---------------- fused attention (+ inline px instance norm) ----------------
__global__ void __launch_bounds__(256) attn_fused(
    const float* __restrict__ ph, const float* __restrict__ pxr,
    const float* __restrict__ aw, const float* __restrict__ fc_w,
    const float* __restrict__ fc_b, float* __restrict__ out_map,
    float* __restrict__ out_fc)
{
    int b = blockIdx.x, tid = threadIdx.x;
    int w = tid >> 5, ln = tid & 31;
    __shared__ __align__(16) float aws[HH];
    __shared__ __align__(16) float mu_s[HH], rs_s[HH];
    __shared__ float ws[8][HH], ws2[8][HH];
    __shared__ float s_s[TT];
    __shared__ float red[8];
    __shared__ float bc;
    __shared__ float ctx2[2][HH];

    if (tid < HH) aws[tid] = aw[tid];

    {
        float s[4] = {0,0,0,0}, s2[4] = {0,0,0,0};
        const float* base = pxr + (size_t)b*TT*HH;
        for (int t = w*32; t < (w+1)*32; t++) {
            const float* row = base + (size_t)t*HH;
            #pragma unroll
            for (int j = 0; j < 4; j++) {
                float v = row[ln + 32*j];
                s[j] += v; s2[j] += v*v;
            }
        }
        #pragma unroll
        for (int j = 0; j < 4; j++) { ws[w][ln+32*j] = s[j]; ws2[w][ln+32*j] = s2[j]; }
        __syncthreads();
        if (tid < HH) {
            float S = 0.f, S2 = 0.f;
            #pragma unroll
            for (int i = 0; i < 8; i++) { S += ws[i][tid]; S2 += ws2[i][tid]; }
            float m = S / (float)TT;
            float var = S2 / (float)TT - m*m;
            mu_s[tid] = m;
            rs_s[tid] = rsqrtf(var + EPSF);
        }
    }
    __syncthreads();

    const float4* aw4 = reinterpret_cast<const float4*>(aws);
    const float4* mu4 = reinterpret_cast<const float4*>(mu_s);
    const float4* rs4 = reinterpret_cast<const float4*>(rs_s);
    float4 av = aw4[ln], am = mu4[ln], ar = rs4[ln];
    #pragma unroll 1
    for (int i = 0; i < 32; i++) {
        int t = w*32 + i;
        const float4* p4 = reinterpret_cast<const float4*>(ph + ((size_t)(b*TT + t))*HH);
        const float4* x4 = reinterpret_cast<const float4*>(pxr + ((size_t)(b*TT + t))*HH);
        float4 a = p4[ln], c4 = x4[ln];
        float v = ftanh(a.x + (c4.x - am.x)*ar.x)*av.x
                + ftanh(a.y + (c4.y - am.y)*ar.y)*av.y
                + ftanh(a.z + (c4.z - am.z)*ar.z)*av.z
                + ftanh(a.w + (c4.w - am.w)*ar.w)*av.w;
        v = warpSum(v);
        if (ln == 0) s_s[t] = v;
    }
    __syncthreads();

    float v = s_s[tid];
    float m = v;
    #pragma unroll
    for (int o = 16; o > 0; o >>= 1) m = fmaxf(m, __shfl_xor_sync(0xffffffffu, m, o));
    if (ln == 0) red[w] = m;
    __syncthreads();
    if (tid == 0) {
        float M = red[0];
        for (int i = 1; i < 8; i++) M = fmaxf(M, red[i]);
        bc = M;
    }
    __syncthreads();
    float e = expf(v - bc);
    float s = warpSum(e);
    if (ln == 0) red[w] = s;
    __syncthreads();
    if (tid == 0) {
        float S = 0.f;
        for (int i = 0; i < 8; i++) S += red[i];
        bc = S;
    }
    __syncthreads();
    float p = e / bc;
    s_s[tid] = p;
    __syncthreads();

    const float inv = 1.0f / (float)DD;
    const size_t base = (size_t)b*TT*DD;
    for (int idx = tid; idx < TT*DD; idx += 256)
        out_map[base + idx] = s_s[idx >> 7] * inv;

    {
        int h = tid & 127, half = tid >> 7;
        float acc = 0.f;
        const float* pb = ph + (size_t)(b*TT + half*128)*HH + h;
        #pragma unroll 4
        for (int t = 0; t < 128; t++)
            acc += pb[(size_t)t*HH] * s_s[half*128 + t];
        ctx2[half][h] = acc;
    }
    __syncthreads();
    if (tid < NC) {
        float acc = fc_b[tid];
        for (int kk = 0; kk < HH; kk++)
            acc += (ctx2[0][kk] + ctx2[1][kk]) * fc_w[tid*HH + kk];
        out_fc[b*NC + tid] = acc;
    }
}

// ---------------- launch ----------------
extern "C" void kernel_launch(void* const* d_in, const int* in_sizes, int n_in,
                              void* d_out, int out_size)
{
    (void)in_sizes; (void)n_in;
    const float* x        = (const float*)d_in[0];
    const float* Wih      = (const float*)d_in[1];
    const float* Whh      = (const float*)d_in[2];
    const float* bih      = (const float*)d_in[3];
    const float* bhh      = (const float*)d_in[4];
    const float* proj_h_w = (const float*)d_in[5];
    const float* proj_h_b = (const float*)d_in[6];
    const float* proj_x_w = (const float*)d_in[7];
    const float* proj_x_b = (const float*)d_in[8];
    const float* attn_w   = (const float*)d_in[9];
    const float* fc_w     = (const float*)d_in[10];
    const float* fc_b     = (const float*)d_in[11];

    float *p_x2, *p_hall, *p_hst, *p_cst, *p_ph, *p_pxr, *p_hmu, *p_hrs, *p_fc_s, *p_map_s;
    cudaGetSymbolAddress((void**)&p_x2,   g_x2);
    cudaGetSymbolAddress((void**)&p_hall, g_hall);
    cudaGetSymbolAddress((void**)&p_hst,  g_hstate);
    cudaGetSymbolAddress((void**)&p_cst,  g_cstate);
    cudaGetSymbolAddress((void**)&p_ph,   g_ph);
    cudaGetSymbolAddress((void**)&p_pxr,  g_pxr);
    cudaGetSymbolAddress((void**)&p_hmu,  g_hmu);
    cudaGetSymbolAddress((void**)&p_hrs,  g_hrs);
    cudaGetSymbolAddress((void**)&p_fc_s, g_fc_scratch);
    cudaGetSymbolAddress((void**)&p_map_s, g_map_scratch);

    float* outf = (float*)d_out;
    float* out_fc;
    float* out_map;
    if (out_size >= BB*NC + BT*DD) { out_fc = outf;   out_map = outf + BB*NC; }
    else if (out_size == BT*DD)    { out_map = outf;  out_fc  = p_fc_s; }
    else                           { out_fc = outf;   out_map = p_map_s; }

    const int dynSmem = (CC*256 + CC*128) * 4;   // 49152 bytes
    cudaFuncSetAttribute(lstm_wave, cudaFuncAttributeMaxDynamicSharedMemorySize, dynSmem);

    stats_kernel<<<DD, 256>>>(x);
    norm1_kernel<<<BB*DD, 256>>>(x);

    for (int d = 0; d < NDIAG; d++) {
        int lmin = (d - (KK - 1) > 0) ? d - (KK - 1) : 0;
        int lmax = (d < LL - 1) ? d : LL - 1;
        int ncells = lmax - lmin + 1;
        lstm_wave<<<ncells*BB*2, 256, dynSmem>>>(lmin, d, p_x2, Wih, Whh, bih, bhh,
                                                 p_hall, p_hst, p_cst);
    }

    const float* lstm_out = p_hall + (size_t)3*BT*HH;
    colstats_kernel<<<BB, 256>>>(lstm_out, p_hmu, p_hrs);
    proj_dual_kernel<<<2*(BT/16), 128>>>(lstm_out, proj_h_w, proj_h_b, p_hmu, p_hrs, p_ph,
                                         p_x2, proj_x_w, proj_x_b, p_pxr);

    attn_fused<<<BB, 256>>>(p_ph, p_pxr, attn_w, fc_w, fc_b, out_map, out_fc);
}

// round 17
// speedup vs baseline: 1.1205x; 1.1205x over previous
#include <cuda_runtime.h>
#include <math.h>
#include <stdint.h>

#define BB 16
#define TT 256
#define DD 128
#define HH 128
#define LL 4
#define GG (4*HH)      // 512 gates
#define NC 10
#define EPSF 1e-5f
#define BT (BB*TT)     // 4096
#define CC 8           // chunk length
#define KK (TT/CC)     // 32 chunks

// ---------------- scratch (device globals; no allocation allowed) ----------------
__device__ float g_x2[BT*DD];
__device__ float g_hall[LL*BT*HH];    // per-layer hidden outputs
__device__ int   g_flag[LL*BB*KK*2];  // chunk-publish flags (pairs, 8B aligned)
__device__ float g_ph[BT*HH];
__device__ float g_pxr[BT*HH];
__device__ float g_mu[DD];
__device__ float g_sd[DD];
__device__ float g_hmu[BB*HH];
__device__ float g_hrs[BB*HH];
__device__ float g_fc_scratch[BB*NC];
__device__ float g_map_scratch[BT*DD];

// ---------------- helpers ----------------
__device__ __forceinline__ float warpSum(float v) {
    #pragma unroll
    for (int o = 16; o > 0; o >>= 1) v += __shfl_xor_sync(0xffffffffu, v, o);
    return v;
}
// HW tanh (sm_75+): 1 MUFU op, ~2e-5 rel err
__device__ __forceinline__ float ftanh(float x) {
    float y;
    asm("tanh.approx.f32 %0, %1;" : "=f"(y) : "f"(x));
    return y;
}
__device__ __forceinline__ float fsig2(float x) {            // sigmoid via HW tanh
    return fmaf(ftanh(x * 0.5f), 0.5f, 0.5f);
}
__device__ __forceinline__ unsigned int smem_u32(const void* p) {
    unsigned int a;
    asm("{ .reg .u64 t; cvta.to.shared.u64 t, %1; cvt.u32.u64 %0, t; }" : "=r"(a) : "l"(p));
    return a;
}
__device__ __forceinline__ unsigned int mapa_u32(unsigned int local, unsigned int rank) {
    unsigned int r;
    asm("mapa.shared::cluster.u32 %0, %1, %2;" : "=r"(r) : "r"(local), "r"(rank));
    return r;
}
__device__ __forceinline__ void fma2(unsigned long long& acc, unsigned long long a, unsigned long long b) {
    asm("fma.rn.f32x2 %0, %1, %2, %0;" : "+l"(acc) : "l"(a), "l"(b));
}
__device__ __forceinline__ void mbar_init(unsigned int addr, unsigned int cnt) {
    asm volatile("mbarrier.init.shared.b64 [%0], %1;" :: "r"(addr), "r"(cnt) : "memory");
}
__device__ __forceinline__ void mbar_expect_tx(unsigned int addr, unsigned int bytes) {
    asm volatile("mbarrier.arrive.expect_tx.shared.b64 _, [%0], %1;" :: "r"(addr), "r"(bytes) : "memory");
}
__device__ __forceinline__ void bulk_send(unsigned int dst_cluster, unsigned int src_cta,
                                          unsigned int bytes, unsigned int remote_mbar) {
    asm volatile("cp.async.bulk.shared::cluster.shared::cta.mbarrier::complete_tx::bytes "
                 "[%0], [%1], %2, [%3];"
                 :: "r"(dst_cluster), "r"(src_cta), "r"(bytes), "r"(remote_mbar) : "memory");
}
__device__ __forceinline__ void fence_proxy_async_cta() {
    asm volatile("fence.proxy.async.shared::cta;" ::: "memory");
}
__device__ __forceinline__ void bar_wait_acq_cta(unsigned int addr, int parity) {
    asm volatile(
        "{\n\t"
        ".reg .pred P;\n\t"
        "BWL_%=:\n\t"
        "mbarrier.try_wait.parity.acquire.cta.shared::cta.b64 P, [%0], %1, 0x989680;\n\t"
        "@P bra BWD_%=;\n\t"
        "bra BWL_%=;\n\t"
        "BWD_%=:\n\t"
        "}"
        :: "r"(addr), "r"(parity) : "memory");
}
__device__ __forceinline__ unsigned long long ld_acquire64(const int* p) {
    unsigned long long v;
    asm volatile("ld.acquire.gpu.global.b64 %0, [%1];" : "=l"(v) : "l"(p) : "memory");
    return v;
}
__device__ __forceinline__ void st_release(int* p, int v) {
    asm volatile("st.release.gpu.global.b32 [%0], %1;" :: "l"(p), "r"(v) : "memory");
}

// ---------------- flag reset (graph-replay safe) ----------------
__global__ void zero_flags_kernel(int* flags) {
    for (int i = threadIdx.x; i < LL*BB*KK*2; i += blockDim.x) flags[i] = 0;
}

// ---------------- per-feature global mean / std (ddof=1), std+EPS ----------------
__global__ void stats_kernel(const float* __restrict__ x) {
    int d = blockIdx.x;
    float s = 0.f, s2 = 0.f;
    for (int i = threadIdx.x; i < BT; i += blockDim.x) {
        float v = x[i*DD + d];
        s += v; s2 += v*v;
    }
    __shared__ float sh[64];
    s = warpSum(s); s2 = warpSum(s2);
    int w = threadIdx.x >> 5, ln = threadIdx.x & 31;
    if (ln == 0) { sh[w] = s; sh[32+w] = s2; }
    __syncthreads();
    if (threadIdx.x == 0) {
        float S = 0.f, S2 = 0.f;
        int nw = blockDim.x >> 5;
        for (int i = 0; i < nw; i++) { S += sh[i]; S2 += sh[32+i]; }
        float m = S / (float)BT;
        float var = (S2 - (float)BT*m*m) / ((float)BT - 1.0f);
        g_mu[d] = m;
        g_sd[d] = sqrtf(var) + EPSF;
    }
}

// ---------------- global normalize + instance norm over T, fused ----------------
__global__ void norm1_kernel(const float* __restrict__ x) {
    int b = blockIdx.x / DD, d = blockIdx.x % DD;
    int t = threadIdx.x;
    float mu = g_mu[d], sd = g_sd[d];
    float v = x[((b*TT) + t)*DD + d];
    float x1 = (v - mu) / sd;
    __shared__ float sh[16];
    float s = warpSum(x1), s2 = warpSum(x1*x1);
    int w = t >> 5, ln = t & 31;
    if (ln == 0) { sh[w] = s; sh[8+w] = s2; }
    __syncthreads();
    __shared__ float mm, rs;
    if (t == 0) {
        float S = 0.f, S2 = 0.f;
        for (int i = 0; i < 8; i++) { S += sh[i]; S2 += sh[8+i]; }
        float m = S / (float)TT;
        float var = S2 / (float)TT - m*m;
        mm = m; rs = rsqrtf(var + EPSF);
    }
    __syncthreads();
    g_x2[((b*TT) + t)*DD + d] = (x1 - mm) * rs;
}

// ---------------- column stats over T per (b,c) ----------------
__global__ void __launch_bounds__(256) colstats_kernel(
    const float* __restrict__ in, float* __restrict__ mu_o, float* __restrict__ rs_o)
{
    int b = blockIdx.x;
    int w = threadIdx.x >> 5, ln = threadIdx.x & 31;
    __shared__ float ws[8][HH], ws2[8][HH];
    float s[4] = {0,0,0,0}, s2[4] = {0,0,0,0};
    const float* base = in + (size_t)b*TT*HH;
    for (int t = w*32; t < (w+1)*32; t++) {
        const float* row = base + (size_t)t*HH;
        #pragma unroll
        for (int j = 0; j < 4; j++) {
            float v = row[ln + 32*j];
            s[j] += v; s2[j] += v*v;
        }
    }
    #pragma unroll
    for (int j = 0; j < 4; j++) { ws[w][ln + 32*j] = s[j]; ws2[w][ln + 32*j] = s2[j]; }
    __syncthreads();
    if (threadIdx.x < HH) {
        int c = threadIdx.x;
        float S = 0.f, S2 = 0.f;
        #pragma unroll
        for (int i = 0; i < 8; i++) { S += ws[i][c]; S2 += ws2[i][c]; }
        float m = S / (float)TT;
        float var = S2 / (float)TT - m*m;
        mu_o[b*HH + c] = m;
        rs_o[b*HH + c] = rsqrtf(var + EPSF);
    }
}

// ---------------- dual projection GEMM: ph (normalized) and pxr in ONE launch ----
__global__ void __launch_bounds__(128, 4) proj_dual_kernel(
    const float* __restrict__ A1, const float* __restrict__ W1,
    const float* __restrict__ b1, const float* __restrict__ mu,
    const float* __restrict__ rs, float* __restrict__ C1,
    const float* __restrict__ A2, const float* __restrict__ W2,
    const float* __restrict__ b2, float* __restrict__ C2)
{
    __shared__ __align__(16) float As[16*128];
    const bool second = blockIdx.x >= 256;
    const int m0 = (second ? (blockIdx.x - 256) : blockIdx.x) * 16;
    const float* A = second ? A2 : A1;
    const float* W = second ? W2 : W1;
    const float* bb = second ? b2 : b1;
    float* C = second ? C2 : C1;

    if (!second) {
        __shared__ float mu_s[128], rs_s[128];
        int b = m0 / TT;
        if (threadIdx.x < 128) {
            mu_s[threadIdx.x] = mu[b*HH + threadIdx.x];
            rs_s[threadIdx.x] = rs[b*HH + threadIdx.x];
        }
        __syncthreads();
        for (int idx = threadIdx.x; idx < 16*128; idx += blockDim.x) {
            int k = idx & 127;
            As[idx] = (A[m0*128 + idx] - mu_s[k]) * rs_s[k];
        }
    } else {
        for (int idx = threadIdx.x; idx < 16*128; idx += blockDim.x)
            As[idx] = A[m0*128 + idx];
    }
    __syncthreads();
    int j = threadIdx.x;
    float bias = bb[j];
    float acc[16];
    #pragma unroll
    for (int mi = 0; mi < 16; mi++) acc[mi] = bias;
    const float4* W4 = reinterpret_cast<const float4*>(W) + j*32;
    for (int k4 = 0; k4 < 32; k4++) {
        float4 w = W4[k4];
        #pragma unroll
        for (int mi = 0; mi < 16; mi++) {
            float4 a = *reinterpret_cast<const float4*>(&As[mi*128 + k4*4]);
            acc[mi] += a.x*w.x + a.y*w.y + a.z*w.z + a.w*w.w;
        }
    }
    #pragma unroll
    for (int mi = 0; mi < 16; mi++) C[(m0+mi)*HH + j] = acc[mi];
}

// ==================== persistent wavefront LSTM (R14 champion + faster flag poll) ==
// 64 clusters (cid = l*16+b) x 2 CTAs. Whh rows in regs; layer handoff via gmem
// flags (64-bit combined acquire poll) gating CC-step chunks. Phase A streams
// Wih per chunk for ALL layers (layer 0 consumes x2 directly).
__global__ void __launch_bounds__(256, 1) __cluster_dims__(2, 1, 1)
lstm_persist(const float* __restrict__ x2,
             const float* __restrict__ Wih, const float* __restrict__ Whh,
             const float* __restrict__ bih, const float* __restrict__ bhh,
             float* __restrict__ hall, int* __restrict__ flags)
{
    __shared__ __align__(16) float hbuf[2][HH];
    __shared__ __align__(16) float hin_s[CC*HH];
    __shared__ float gates_s[256];
    __shared__ __align__(8) unsigned long long barF[2];

    const int cid = blockIdx.x >> 1;
    const int l   = cid >> 4;           // 0..3
    const int b   = cid & 15;
    const int q   = blockIdx.x & 1;
    const int tid = threadIdx.x;
    const int gtype = tid >> 6, u = tid & 63;
    const int row_g = gtype*HH + q*64 + u;

    unsigned long long w[64];
    {
        const float* Wrow = Whh + ((size_t)l*GG + row_g)*HH;
        const unsigned long long* WpS = reinterpret_cast<const unsigned long long*>(Wrow + q*64);
        const unsigned long long* WpP = reinterpret_cast<const unsigned long long*>(Wrow + (q^1)*64);
        #pragma unroll
        for (int i = 0; i < 32; i++) { w[i] = WpS[i]; w[32+i] = WpP[i]; }
    }
    const float bias = bih[l*GG + row_g] + bhh[l*GG + row_g];
    const float4* Wih4 = reinterpret_cast<const float4*>(Wih + ((size_t)l*GG + row_g)*HH);

    if (tid < HH) hbuf[0][tid] = 0.f;
    float c = 0.f;

    const unsigned int barF_loc = smem_u32(&barF[0]);
    if (tid == 0) {
        mbar_init(barF_loc,     1);
        mbar_init(barF_loc + 8, 1);
    }
    __syncthreads();
    if (tid == 64) {
        mbar_expect_tx(barF_loc + 8, 256u);
        mbar_expect_tx(barF_loc,     256u);
    }
    unsigned int srcH[2], dstH[2], dstB[2];
    if (tid == 0) {
        unsigned int h0 = smem_u32(&hbuf[0][q*64]);
        unsigned int h1 = smem_u32(&hbuf[1][q*64]);
        unsigned int pr = q ^ 1;
        srcH[0] = h0;               srcH[1] = h1;
        dstH[0] = mapa_u32(h0, pr); dstH[1] = mapa_u32(h1, pr);
        dstB[0] = mapa_u32(barF_loc,     pr);
        dstB[1] = mapa_u32(barF_loc + 8, pr);
    }
    __syncthreads();
    asm volatile("barrier.cluster.arrive.aligned;" ::: "memory");
    asm volatile("barrier.cluster.wait.aligned;"   ::: "memory");

    float* hout = hall + ((size_t)l*BT + b*TT)*HH + q*64;
    const float* in_base = (l == 0) ? (x2 + (size_t)b*TT*DD)
                                    : (hall + ((size_t)(l-1)*BT + b*TT)*HH);
    int pF[2] = {0, 0};
    const int selfOff = q*64, partOff = (q^1)*64;
    const unsigned long long BOTH = 0x0000000100000001ULL;

    for (int k = 0; k < KK; k++) {
        // ---- acquire this chunk's input (phase A) ----
        if (l > 0) {
            if (tid == 0) {
                const int* f0 = flags + (((l-1)*BB + b)*KK + k)*2;
                while (ld_acquire64(f0) != BOTH) __nanosleep(32);
            }
            __syncthreads();
        }
        const float* hsrc = in_base + (size_t)(k*CC)*HH;
        for (int idx = tid; idx < CC*HH; idx += 256) hin_s[idx] = hsrc[idx];
        __syncthreads();

        float gacc[CC];
        {
            unsigned long long acc[CC];
            #pragma unroll
            for (int s = 0; s < CC; s++) acc[s] = 0ULL;
            #pragma unroll 4
            for (int j = 0; j < 32; j++) {
                float4 wv = __ldg(&Wih4[j]);
                unsigned long long wA, wB;
                asm("mov.b64 %0, {%1, %2};" : "=l"(wA) : "f"(wv.x), "f"(wv.y));
                asm("mov.b64 %0, {%1, %2};" : "=l"(wB) : "f"(wv.z), "f"(wv.w));
                #pragma unroll
                for (int s = 0; s < CC; s++) {
                    const ulonglong2 hv = *reinterpret_cast<const ulonglong2*>(&hin_s[s*HH + 4*j]);
                    fma2(acc[s], wA, hv.x);
                    fma2(acc[s], wB, hv.y);
                }
            }
            #pragma unroll
            for (int s = 0; s < CC; s++)
                gacc[s] = bias
                    + __uint_as_float((unsigned)(acc[s] & 0xffffffffULL))
                    + __uint_as_float((unsigned)(acc[s] >> 32));
        }
        __syncthreads();

        // ---- phase B: CC recurrence steps ----
        #pragma unroll 1
        for (int s = 0; s < CC; s++) {
            const int t = k*CC + s;
            const int sl = t & 1;
            unsigned long long a0 = 0ULL, a1 = 0ULL;
            {
                const ulonglong2* Hs = reinterpret_cast<const ulonglong2*>(&hbuf[sl][selfOff]);
                #pragma unroll
                for (int i = 0; i < 16; i++) {
                    ulonglong2 h2 = Hs[i];
                    fma2(a0, w[2*i],   h2.x);
                    fma2(a1, w[2*i+1], h2.y);
                }
            }
            if (t >= 1) {
                bar_wait_acq_cta(barF_loc + 8*sl, pF[sl]); pF[sl] ^= 1;
                if (tid == 64 && t + 2 < TT) mbar_expect_tx(barF_loc + 8*sl, 256u);
            }
            {
                const ulonglong2* Hp = reinterpret_cast<const ulonglong2*>(&hbuf[sl][partOff]);
                #pragma unroll
                for (int i = 0; i < 16; i++) {
                    ulonglong2 h2 = Hp[i];
                    fma2(a0, w[32 + 2*i], h2.x);
                    fma2(a1, w[33 + 2*i], h2.y);
                }
            }
            gates_s[tid] = gacc[s]
                + __uint_as_float((unsigned)(a0 & 0xffffffffULL))
                + __uint_as_float((unsigned)(a0 >> 32))
                + __uint_as_float((unsigned)(a1 & 0xffffffffULL))
                + __uint_as_float((unsigned)(a1 >> 32));
            __syncthreads();

            if (tid < 64) {
                float gi = gates_s[tid],       gf = gates_s[64 + tid];
                float gg = gates_s[128 + tid], go = gates_s[192 + tid];
                float si = fsig2(gi), sf = fsig2(gf), so = fsig2(go);
                float tg = ftanh(gg);
                c = sf*c + si*tg;
                float hn = so * ftanh(c);
                if (t + 1 < TT) hbuf[(t + 1) & 1][selfOff + tid] = hn;
                hout[(size_t)t*HH + tid] = hn;
            }
            __syncthreads();
            if (tid == 0 && t + 1 < TT) {
                int ns = (t + 1) & 1;
                fence_proxy_async_cta();
                bulk_send(dstH[ns], srcH[ns], 256u, dstB[ns]);
            }
        }

        // ---- publish chunk to layer l+1 ----
        if (l < LL - 1 && tid == 0) {
            __threadfence();
            st_release(flags + ((l*BB + b)*KK + k)*2 + q, 1);
        }
    }
    asm volatile("barrier.cluster.arrive.aligned;" ::: "memory");
    asm volatile("barrier.cluster.wait.aligned;"   ::: "memory");
}

// ---------------- fused attention (+ inline px instance norm) ----------------
__global__ void __launch_bounds__(256) attn_fused(
    const float* __restrict__ ph, const float* __restrict__ pxr,
    const float* __restrict__ aw, const float* __restrict__ fc_w,
    const float* __restrict__ fc_b, float* __restrict__ out_map,
    float* __restrict__ out_fc)
{
    int b = blockIdx.x, tid = threadIdx.x;
    int w = tid >> 5, ln = tid & 31;
    __shared__ __align__(16) float aws[HH];
    __shared__ __align__(16) float mu_s[HH], rs_s[HH];
    __shared__ float ws[8][HH], ws2[8][HH];
    __shared__ float s_s[TT];
    __shared__ float red[8];
    __shared__ float bc;
    __shared__ float ctx2[2][HH];

    if (tid < HH) aws[tid] = aw[tid];

    {
        float s[4] = {0,0,0,0}, s2[4] = {0,0,0,0};
        const float* base = pxr + (size_t)b*TT*HH;
        for (int t = w*32; t < (w+1)*32; t++) {
            const float* row = base + (size_t)t*HH;
            #pragma unroll
            for (int j = 0; j < 4; j++) {
                float v = row[ln + 32*j];
                s[j] += v; s2[j] += v*v;
            }
        }
        #pragma unroll
        for (int j = 0; j < 4; j++) { ws[w][ln+32*j] = s[j]; ws2[w][ln+32*j] = s2[j]; }
        __syncthreads();
        if (tid < HH) {
            float S = 0.f, S2 = 0.f;
            #pragma unroll
            for (int i = 0; i < 8; i++) { S += ws[i][tid]; S2 += ws2[i][tid]; }
            float m = S / (float)TT;
            float var = S2 / (float)TT - m*m;
            mu_s[tid] = m;
            rs_s[tid] = rsqrtf(var + EPSF);
        }
    }
    __syncthreads();

    const float4* aw4 = reinterpret_cast<const float4*>(aws);
    const float4* mu4 = reinterpret_cast<const float4*>(mu_s);
    const float4* rs4 = reinterpret_cast<const float4*>(rs_s);
    float4 av = aw4[ln], am = mu4[ln], ar = rs4[ln];
    #pragma unroll 1
    for (int i = 0; i < 32; i++) {
        int t = w*32 + i;
        const float4* p4 = reinterpret_cast<const float4*>(ph + ((size_t)(b*TT + t))*HH);
        const float4* x4 = reinterpret_cast<const float4*>(pxr + ((size_t)(b*TT + t))*HH);
        float4 a = p4[ln], c4 = x4[ln];
        float v = ftanh(a.x + (c4.x - am.x)*ar.x)*av.x
                + ftanh(a.y + (c4.y - am.y)*ar.y)*av.y
                + ftanh(a.z + (c4.z - am.z)*ar.z)*av.z
                + ftanh(a.w + (c4.w - am.w)*ar.w)*av.w;
        v = warpSum(v);
        if (ln == 0) s_s[t] = v;
    }
    __syncthreads();

    float v = s_s[tid];
    float m = v;
    #pragma unroll
    for (int o = 16; o > 0; o >>= 1) m = fmaxf(m, __shfl_xor_sync(0xffffffffu, m, o));
    if (ln == 0) red[w] = m;
    __syncthreads();
    if (tid == 0) {
        float M = red[0];
        for (int i = 1; i < 8; i++) M = fmaxf(M, red[i]);
        bc = M;
    }
    __syncthreads();
    float e = expf(v - bc);
    float s = warpSum(e);
    if (ln == 0) red[w] = s;
    __syncthreads();
    if (tid == 0) {
        float S = 0.f;
        for (int i = 0; i < 8; i++) S += red[i];
        bc = S;
    }
    __syncthreads();
    float p = e / bc;
    s_s[tid] = p;
    __syncthreads();

    const float inv = 1.0f / (float)DD;
    const size_t base = (size_t)b*TT*DD;
    for (int idx = tid; idx < TT*DD; idx += 256)
        out_map[base + idx] = s_s[idx >> 7] * inv;

    {
        int h = tid & 127, half = tid >> 7;
        float acc = 0.f;
        const float* pb = ph + (size_t)(b*TT + half*128)*HH + h;
        #pragma unroll 4
        for (int t = 0; t < 128; t++)
            acc += pb[(size_t)t*HH] * s_s[half*128 + t];
        ctx2[half][h] = acc;
    }
    __syncthreads();
    if (tid < NC) {
        float acc = fc_b[tid];
        for (int kk = 0; kk < HH; kk++)
            acc += (ctx2[0][kk] + ctx2[1][kk]) * fc_w[tid*HH + kk];
        out_fc[b*NC + tid] = acc;
    }
}

// ---------------- launch ----------------
extern "C" void kernel_launch(void* const* d_in, const int* in_sizes, int n_in,
                              void* d_out, int out_size)
{
    (void)in_sizes; (void)n_in;
    const float* x        = (const float*)d_in[0];
    const float* Wih      = (const float*)d_in[1];
    const float* Whh      = (const float*)d_in[2];
    const float* bih      = (const float*)d_in[3];
    const float* bhh      = (const float*)d_in[4];
    const float* proj_h_w = (const float*)d_in[5];
    const float* proj_h_b = (const float*)d_in[6];
    const float* proj_x_w = (const float*)d_in[7];
    const float* proj_x_b = (const float*)d_in[8];
    const float* attn_w   = (const float*)d_in[9];
    const float* fc_w     = (const float*)d_in[10];
    const float* fc_b     = (const float*)d_in[11];

    float *p_x2, *p_hall, *p_ph, *p_pxr, *p_hmu, *p_hrs, *p_fc_s, *p_map_s;
    int *p_flag;
    cudaGetSymbolAddress((void**)&p_x2,   g_x2);
    cudaGetSymbolAddress((void**)&p_hall, g_hall);
    cudaGetSymbolAddress((void**)&p_flag, g_flag);
    cudaGetSymbolAddress((void**)&p_ph,   g_ph);
    cudaGetSymbolAddress((void**)&p_pxr,  g_pxr);
    cudaGetSymbolAddress((void**)&p_hmu,  g_hmu);
    cudaGetSymbolAddress((void**)&p_hrs,  g_hrs);
    cudaGetSymbolAddress((void**)&p_fc_s, g_fc_scratch);
    cudaGetSymbolAddress((void**)&p_map_s, g_map_scratch);

    float* outf = (float*)d_out;
    float* out_fc;
    float* out_map;
    if (out_size >= BB*NC + BT*DD) { out_fc = outf;   out_map = outf + BB*NC; }
    else if (out_size == BT*DD)    { out_map = outf;  out_fc  = p_fc_s; }
    else                           { out_fc = outf;   out_map = p_map_s; }

    zero_flags_kernel<<<1, 256>>>(p_flag);
    stats_kernel<<<DD, 256>>>(x);
    norm1_kernel<<<BB*DD, 256>>>(x);

    lstm_persist<<<LL*BB*2, 256>>>(p_x2, Wih, Whh, bih, bhh, p_hall, p_flag);

    const float* lstm_out = p_hall + (size_t)3*BT*HH;
    colstats_kernel<<<BB, 256>>>(lstm_out, p_hmu, p_hrs);
    proj_dual_kernel<<<2*(BT/16), 128>>>(lstm_out, proj_h_w, proj_h_b, p_hmu, p_hrs, p_ph,
                                         p_x2, proj_x_w, proj_x_b, p_pxr);

    attn_fused<<<BB, 256>>>(p_ph, p_pxr, attn_w, fc_w, fc_b, out_map, out_fc);
}